// round 5
// baseline (speedup 1.0000x reference)
#include <cuda_runtime.h>
#include <cuda_bf16.h>
#include <math.h>

// ---------------------------------------------------------------------------
// N=1024 nodes, F=128, H=256, complete graph.
//  - GIN aggregation on triu edges == inclusive prefix-sum over rows.
//  - cumsum(X) @ W == cumsum(X @ W)  -> GEMM first, scan after.
//  - leaky(relu(z)) == relu(z).
//  - Edge MLP: hidden = A[src] + B[dst], A = x@ew1[:F]+eb1, B = x@ew1[F:].
// ---------------------------------------------------------------------------

#define NN 1024
#define HH 256

__device__ float g_buf1[NN * HH];
__device__ float g_buf2[NN * HH];
__device__ float g_A[NN * HH];
__device__ float g_B[NN * HH];

typedef unsigned long long u64;

// ---- packed f32x2 helpers (sm_100a) ---------------------------------------
__device__ __forceinline__ u64 add2(u64 a, u64 b) {
    u64 r; asm("add.rn.f32x2 %0, %1, %2;" : "=l"(r) : "l"(a), "l"(b)); return r;
}
__device__ __forceinline__ u64 fma2(u64 a, u64 b, u64 c) {
    u64 r; asm("fma.rn.f32x2 %0, %1, %2, %3;" : "=l"(r) : "l"(a), "l"(b), "l"(c)); return r;
}
__device__ __forceinline__ u64 relu2(u64 t) {
    unsigned lo, hi;
    asm("mov.b64 {%0, %1}, %2;" : "=r"(lo), "=r"(hi) : "l"(t));
    float flo = fmaxf(__uint_as_float(lo), 0.f);
    float fhi = fmaxf(__uint_as_float(hi), 0.f);
    u64 r;
    asm("mov.b64 %0, {%1, %2};" : "=l"(r)
        : "r"(__float_as_uint(flo)), "r"(__float_as_uint(fhi)));
    return r;
}
__device__ __forceinline__ float sum2(u64 t) {
    unsigned lo, hi;
    asm("mov.b64 {%0, %1}, %2;" : "=r"(lo), "=r"(hi) : "l"(t));
    return __uint_as_float(lo) + __uint_as_float(hi);
}

// ---------------------------------------------------------------------------
// GEMM v5: out[M,N] = X[M,K] @ W[K,N] (+bias)(+epilogue)
// TM=16, TN in {64,32}, TK=32, 256 threads, micro 1 x (TN/16).
// Grid = (N/TN, 64[, 2]) = 256 (512 dual) blocks -> 2 CTAs/SM, overlapping
// double-buffered pipelines. One sync per K-iteration.
// DUAL: blockIdx.z==1 computes X @ W2 -> out2 (no bias) in the same launch.
// EPI: 0=none, 1=relu, 2=leaky(0.01)
// ---------------------------------------------------------------------------
template <int K, int N, int TN, int EPI, int DUAL>
__global__ __launch_bounds__(256) void sgemm5(
    const float* __restrict__ X, const float* __restrict__ W,
    const float* __restrict__ W2, const float* __restrict__ bias,
    float* __restrict__ out, float* __restrict__ out2) {

    constexpr int TK  = 32;
    constexpr int MN  = TN / 16;                 // 4 or 2 cols per thread
    constexpr int NIT = K / TK;
    constexpr int WCH = (TK * TN) / (256 * 4);   // W float4 chunks per thread

    __shared__ float As[2][TK][18];              // [buf][k][m], 16 rows + pad
    __shared__ float Bs[2][TK][TN];              // [buf][k][n]

    const int t  = threadIdx.x;
    const int tx = t & 15;
    const int ty = t >> 4;                       // row 0..15
    const int m0 = blockIdx.y * 16;
    const int n0 = blockIdx.x * TN;

    const float* Wp = W;
    const float* bp = bias;
    float*       op = out;
    if (DUAL && blockIdx.z) { Wp = W2; bp = nullptr; op = out2; }

    const bool aload = (t < 128);
    const int xr = t >> 3;                       // 0..15 valid when t<128
    const int xc = (t & 7) * 4;                  // k offset (float4)

    int wr[WCH], wc[WCH];
#pragma unroll
    for (int p = 0; p < WCH; p++) {
        int idx = t + 256 * p;
        wr[p] = (idx * 4) / TN;
        wc[p] = (idx * 4) % TN;
    }

    // prefetch tile 0
    float4 xv = make_float4(0.f, 0.f, 0.f, 0.f);
    if (aload) xv = *(const float4*)&X[(m0 + xr) * K + xc];
    float4 wv[WCH];
#pragma unroll
    for (int p = 0; p < WCH; p++)
        wv[p] = *(const float4*)&Wp[wr[p] * N + n0 + wc[p]];

    // store tile 0 into buffer 0
    if (aload) {
        As[0][xc + 0][xr] = xv.x; As[0][xc + 1][xr] = xv.y;
        As[0][xc + 2][xr] = xv.z; As[0][xc + 3][xr] = xv.w;
    }
#pragma unroll
    for (int p = 0; p < WCH; p++)
        *(float4*)&Bs[0][wr[p]][wc[p]] = wv[p];
    __syncthreads();

    float acc[MN];
#pragma unroll
    for (int j = 0; j < MN; j++) acc[j] = 0.f;

#pragma unroll 1
    for (int it = 0; it < NIT; it++) {
        const int cur = it & 1;
        // issue global prefetch for next tile
        if (it + 1 < NIT) {
            const int k1 = (it + 1) * TK;
            if (aload) xv = *(const float4*)&X[(m0 + xr) * K + k1 + xc];
#pragma unroll
            for (int p = 0; p < WCH; p++)
                wv[p] = *(const float4*)&Wp[(k1 + wr[p]) * N + n0 + wc[p]];
        }
        // compute on current buffer
#pragma unroll
        for (int k = 0; k < TK; k++) {
            float a = As[cur][k][ty];
            if (MN == 4) {
                float4 b = *(const float4*)&Bs[cur][k][tx * 4];
                acc[0] = fmaf(a, b.x, acc[0]);
                acc[1] = fmaf(a, b.y, acc[1]);
                acc[2] = fmaf(a, b.z, acc[2]);
                acc[3] = fmaf(a, b.w, acc[3]);
            } else {
                float2 b = *(const float2*)&Bs[cur][k][tx * 2];
                acc[0] = fmaf(a, b.x, acc[0]);
                acc[1] = fmaf(a, b.y, acc[1]);
            }
        }
        // stage next tile into the other buffer
        if (it + 1 < NIT) {
            const int nxt = cur ^ 1;
            if (aload) {
                As[nxt][xc + 0][xr] = xv.x; As[nxt][xc + 1][xr] = xv.y;
                As[nxt][xc + 2][xr] = xv.z; As[nxt][xc + 3][xr] = xv.w;
            }
#pragma unroll
            for (int p = 0; p < WCH; p++)
                *(float4*)&Bs[nxt][wr[p]][wc[p]] = wv[p];
            __syncthreads();
        }
    }

    {
        int m = m0 + ty;
#pragma unroll
        for (int j = 0; j < MN; j++) {
            int n = n0 + tx * MN + j;
            float v = acc[j];
            if (bp) v += bp[n];
            if (EPI == 1) v = fmaxf(v, 0.f);
            if (EPI == 2) v = (v >= 0.f) ? v : 0.01f * v;
            op[m * N + n] = v;
        }
    }
}

// ---------------------------------------------------------------------------
// Inclusive column prefix-sum over 1024 rows (256 cols), fused BN+relu:
//   h = (cumsum + bias) * (g * rsqrt(1+eps)) + bt ; relu
// ---------------------------------------------------------------------------
__global__ void cumsum_bn_relu_k(const float* __restrict__ in, float* __restrict__ out,
                                 const float* __restrict__ bias, const float* __restrict__ g,
                                 const float* __restrict__ bt) {
    const int C = HH;
    const int c = blockIdx.x;
    const int t = threadIdx.x;
    __shared__ float ssum[256];

    float v[4];
    float run = 0.f;
    const int base = t * 4;
#pragma unroll
    for (int r = 0; r < 4; r++) {
        v[r] = in[(base + r) * C + c];
        run += v[r];
        v[r] = run;
    }
    ssum[t] = run;
    __syncthreads();
    for (int off = 1; off < 256; off <<= 1) {
        float addv = 0.f;
        if (t >= off) addv = ssum[t - off];
        __syncthreads();
        if (t >= off) ssum[t] += addv;
        __syncthreads();
    }
    float excl = (t > 0) ? ssum[t - 1] : 0.f;
    float sc   = g[c] * rsqrtf(1.f + 1e-5f);
    float bb   = bias[c];
    float btc  = bt[c];
#pragma unroll
    for (int r = 0; r < 4; r++) {
        float h = (v[r] + excl + bb) * sc + btc;
        out[(base + r) * C + c] = fmaxf(h, 0.f);
    }
}

// ---------------------------------------------------------------------------
// Edge kernel v3: 64x64 pair tile, 256 threads, 4x4 micro with STRIDE-16
// column/row mapping (conflict-free LDS), packed f32x2 math:
//   acc2 += f32x2( relu(a+b) ) * w2   (two h-lanes per instruction)
// p(i,j) = sigmoid(sum_h relu(A[i,h]+B[j,h]) * w[h] + eb2); both halves + diag.
// ---------------------------------------------------------------------------
#define ESA 256
#define ESB 260
#define EDGE_SMEM ((64 * ESA + 64 * ESB + 256) * 4)

__global__ __launch_bounds__(256) void edge_k(
    const float* __restrict__ A, const float* __restrict__ Bm,
    const float* __restrict__ ew2, const float* __restrict__ eb2,
    float* __restrict__ out) {
    const int ti = blockIdx.y, tj = blockIdx.x;
    if (tj < ti) return;

    extern __shared__ float sh[];
    float* As = sh;                       // 64 * 256 (rows broadcast -> no pad)
    float* Bs = sh + 64 * ESA;            // 64 * 260 (pad: stride-1 rows/lane)
    float* ws = sh + 64 * ESA + 64 * ESB; // 256

    const int t = threadIdx.x;
    ws[t] = ew2[t];

    const int i0 = ti * 64, j0 = tj * 64;
#pragma unroll
    for (int p = 0; p < 16; p++) {
        int q = t + 256 * p;              // 0..4095 float4 chunks
        int r = q >> 6;                   // row 0..63
        int c = (q & 63) << 2;            // col
        *(float4*)&As[r * ESA + c] = *(const float4*)&A[(i0 + r) * HH + c];
        *(float4*)&Bs[r * ESB + c] = *(const float4*)&Bm[(j0 + r) * HH + c];
    }
    __syncthreads();

    const int tx = t & 15, ty = t >> 4;

    u64 acc[4][4];
#pragma unroll
    for (int di = 0; di < 4; di++)
#pragma unroll
        for (int dj = 0; dj < 4; dj++) acc[di][dj] = 0ull;

#pragma unroll 2
    for (int h = 0; h < HH; h += 4) {
        u64 w01 = *(const u64*)&ws[h];
        u64 w23 = *(const u64*)&ws[h + 2];
        u64 a01[4], a23[4], b01[4], b23[4];
#pragma unroll
        for (int d = 0; d < 4; d++) {
            ulonglong2 av = *(const ulonglong2*)&As[(ty + 16 * d) * ESA + h];
            a01[d] = av.x; a23[d] = av.y;
            ulonglong2 bv = *(const ulonglong2*)&Bs[(tx + 16 * d) * ESB + h];
            b01[d] = bv.x; b23[d] = bv.y;
        }
#pragma unroll
        for (int di = 0; di < 4; di++) {
#pragma unroll
            for (int dj = 0; dj < 4; dj++) {
                acc[di][dj] = fma2(relu2(add2(a01[di], b01[dj])), w01, acc[di][dj]);
                acc[di][dj] = fma2(relu2(add2(a23[di], b23[dj])), w23, acc[di][dj]);
            }
        }
    }

    const float e2 = eb2[0];
#pragma unroll
    for (int di = 0; di < 4; di++) {
#pragma unroll
        for (int dj = 0; dj < 4; dj++) {
            int gi = i0 + ty + 16 * di;
            int gj = j0 + tx + 16 * dj;
            float s = sum2(acc[di][dj]) + e2;
            if (gi < gj) {
                float pv = 1.f / (1.f + __expf(-s));
                out[gi * NN + gj] = pv;
                out[gj * NN + gi] = pv;
            } else if (gi == gj) {
                out[gi * NN + gi] = 0.f;
            }
        }
    }
}

// ---------------------------------------------------------------------------
extern "C" void kernel_launch(void* const* d_in, const int* in_sizes, int n_in,
                              void* d_out, int out_size) {
    (void)in_sizes; (void)n_in; (void)out_size;
    const float* x0  = (const float*)d_in[0];
    const float* w1a = (const float*)d_in[1];
    const float* b1a = (const float*)d_in[2];
    const float* g1  = (const float*)d_in[3];
    const float* bt1 = (const float*)d_in[4];
    const float* w1b = (const float*)d_in[5];
    const float* b1b = (const float*)d_in[6];
    const float* w2a = (const float*)d_in[7];
    const float* b2a = (const float*)d_in[8];
    const float* g2  = (const float*)d_in[9];
    const float* bt2 = (const float*)d_in[10];
    const float* w2b = (const float*)d_in[11];
    const float* b2b = (const float*)d_in[12];
    const float* lw1 = (const float*)d_in[13];
    const float* lb1 = (const float*)d_in[14];
    const float* lw2 = (const float*)d_in[15];
    const float* lb2 = (const float*)d_in[16];
    const float* ew1 = (const float*)d_in[17];
    const float* eb1 = (const float*)d_in[18];
    const float* ew2 = (const float*)d_in[19];
    const float* eb2 = (const float*)d_in[20];
    float* out = (float*)d_out;

    float *B1, *B2, *Ap, *Bp;
    cudaGetSymbolAddress((void**)&B1, g_buf1);
    cudaGetSymbolAddress((void**)&B2, g_buf2);
    cudaGetSymbolAddress((void**)&Ap, g_A);
    cudaGetSymbolAddress((void**)&Bp, g_B);

    const dim3 blk(256);
    const dim3 gA(4, 64);        // N=256, TN=64 -> 256 blocks
    const dim3 gB(4, 64);        // N=128, TN=32 -> 256 blocks
    const dim3 gD(4, 64, 2);     // dual edge GEMM -> 512 blocks

    // GIN layer 1
    sgemm5<128, 256, 64, 0, 0><<<gA, blk>>>(x0, w1a, nullptr, nullptr, B1, nullptr);
    cumsum_bn_relu_k<<<256, 256>>>(B1, B2, b1a, g1, bt1);
    sgemm5<256, 256, 64, 1, 0><<<gA, blk>>>(B2, w1b, nullptr, b1b, B1, nullptr);

    // GIN layer 2
    sgemm5<256, 256, 64, 0, 0><<<gA, blk>>>(B1, w2a, nullptr, nullptr, B2, nullptr);
    cumsum_bn_relu_k<<<256, 256>>>(B2, B1, b2a, g2, bt2);
    sgemm5<256, 128, 32, 1, 0><<<gB, blk>>>(B1, w2b, nullptr, b2b, B2, nullptr);

    // Linear head
    sgemm5<128, 256, 64, 2, 0><<<gA, blk>>>(B2, lw1, nullptr, lb1, B1, nullptr);
    sgemm5<256, 128, 32, 0, 0><<<gB, blk>>>(B1, lw2, nullptr, lb2, B2, nullptr);

    // Edge halves in one launch: A = x@ew1[:128]+eb1 ; B = x@ew1[128:]
    sgemm5<128, 256, 64, 0, 1><<<gD, blk>>>(B2, ew1, ew1 + 128 * HH, eb1, Ap, Bp);

    // Pairwise edge probabilities
    (void)cudaFuncSetAttribute(edge_k, cudaFuncAttributeMaxDynamicSharedMemorySize, EDGE_SMEM);
    edge_k<<<dim3(16, 16), blk, EDGE_SMEM>>>(Ap, Bp, ew2, eb2, out);
}

// round 6
// speedup vs baseline: 1.2214x; 1.2214x over previous
#include <cuda_runtime.h>
#include <cuda_bf16.h>
#include <math.h>

// ---------------------------------------------------------------------------
// N=1024 nodes, F=128, H=256, complete graph.
//  - GIN aggregation on triu edges == inclusive prefix-sum over rows.
//  - cumsum(X) @ W == cumsum(X @ W)  -> GEMM first, scan after.
//  - leaky(relu(z)) == relu(z).
//  - Edge MLP: hidden = A[src] + B[dst], A = x@ew1[:F]+eb1, B = x@ew1[F:].
//  - Split-K GEMMs (2 partials); activations/bias fused into CONSUMER loads.
// ---------------------------------------------------------------------------

#define NN 1024
#define HH 256

__device__ float g_s0[NN * HH];
__device__ float g_s1[NN * HH];
__device__ float g_s2[NN * HH];
__device__ float g_s3[NN * HH];
__device__ float g_s4[NN * HH];
__device__ float g_s5[NN * HH];

typedef unsigned long long u64;

// ---- packed f32x2 helpers (sm_100a) ---------------------------------------
__device__ __forceinline__ u64 add2(u64 a, u64 b) {
    u64 r; asm("add.rn.f32x2 %0, %1, %2;" : "=l"(r) : "l"(a), "l"(b)); return r;
}
__device__ __forceinline__ u64 fma2(u64 a, u64 b, u64 c) {
    u64 r; asm("fma.rn.f32x2 %0, %1, %2, %3;" : "=l"(r) : "l"(a), "l"(b), "l"(c)); return r;
}
__device__ __forceinline__ u64 relu2(u64 t) {
    unsigned lo, hi;
    asm("mov.b64 {%0, %1}, %2;" : "=r"(lo), "=r"(hi) : "l"(t));
    float flo = fmaxf(__uint_as_float(lo), 0.f);
    float fhi = fmaxf(__uint_as_float(hi), 0.f);
    u64 r;
    asm("mov.b64 %0, {%1, %2};" : "=l"(r)
        : "r"(__float_as_uint(flo)), "r"(__float_as_uint(fhi)));
    return r;
}
__device__ __forceinline__ float sum2(u64 t) {
    unsigned lo, hi;
    asm("mov.b64 {%0, %1}, %2;" : "=r"(lo), "=r"(hi) : "l"(t));
    return __uint_as_float(lo) + __uint_as_float(hi);
}

// ---------------------------------------------------------------------------
// GEMM v6: out = actA(X0 [+X1] [+ab]) @ W (+bias on z-half 0)
// TM=32, TN in {64,32}, TK=32, 256 threads, 2x(TN/16) micro (R4-proven tile).
// SPLIT: blockIdx.z&1 selects K-half; partial sums to out/outP.
// DUAL:  upper z selects (W,out) vs (W2,out2) — used for the edge-feature pair.
// ALOAD: 0 = X0 ; 1 = X0+X1 ; 2 = relu(X0+X1+ab) ; 3 = leaky(X0+X1+ab)
// Grid = (N/TN, 32, (DUAL?2:1)*(SPLIT?2:1)) -> 256/512 blocks, 2 CTAs/SM.
// ---------------------------------------------------------------------------
template <int KT, int N, int TN, int ALOAD, int DUAL, int SPLIT>
__global__ __launch_bounds__(256) void sgemm6(
    const float* __restrict__ X0, const float* __restrict__ X1,
    const float* __restrict__ ab,
    const float* __restrict__ W, const float* __restrict__ W2,
    const float* __restrict__ bias,
    float* __restrict__ out, float* __restrict__ outP,
    float* __restrict__ out2, float* __restrict__ out2P) {

    constexpr int KB  = SPLIT ? KT / 2 : KT;     // K per block
    constexpr int TK  = 32;
    constexpr int NIT = KB / TK;
    constexpr int MNJ = TN / 16;                 // 4 or 2 cols per thread
    constexpr int WCH = (TK * TN) / (256 * 4);   // W float4 chunks per thread

    __shared__ float As[2][TK][34];
    __shared__ float Bs[2][TK][TN];

    const int t  = threadIdx.x;
    const int tx = t & 15;
    const int ty = t >> 4;
    const int m0 = blockIdx.y * 32;
    const int n0 = blockIdx.x * TN;

    const int z    = blockIdx.z;
    const int half = SPLIT ? (z & 1) : 0;
    const int dsel = DUAL ? (SPLIT ? (z >> 1) : z) : 0;
    const int koff = half * KB;

    const float* Wp = W;
    float* op;
    if (DUAL && dsel) { Wp = W2; op = half ? out2P : out2; }
    else              { op = half ? outP : out; }
    const float* bp = (half == 0 && dsel == 0) ? bias : nullptr;

    const int xr = t >> 3;                       // 0..31 row in X tile
    const int xc = (t & 7) * 4;                  // k offset (float4)

    int wr[WCH], wc[WCH];
#pragma unroll
    for (int p = 0; p < WCH; p++) {
        int idx = t + 256 * p;
        wr[p] = (idx * 4) / TN;
        wc[p] = (idx * 4) % TN;
    }

    // fused A-tile loader (partial-sum combine + bias + activation)
    auto loadA = [&](int kc) -> float4 {
        float4 v = *(const float4*)&X0[(m0 + xr) * KT + kc];
        if (ALOAD >= 1) {
            float4 u = *(const float4*)&X1[(m0 + xr) * KT + kc];
            v.x += u.x; v.y += u.y; v.z += u.z; v.w += u.w;
        }
        if (ALOAD >= 2) {
            float4 bb = *(const float4*)&ab[kc];
            v.x += bb.x; v.y += bb.y; v.z += bb.z; v.w += bb.w;
            if (ALOAD == 2) {
                v.x = fmaxf(v.x, 0.f); v.y = fmaxf(v.y, 0.f);
                v.z = fmaxf(v.z, 0.f); v.w = fmaxf(v.w, 0.f);
            } else {
                v.x = (v.x >= 0.f) ? v.x : 0.01f * v.x;
                v.y = (v.y >= 0.f) ? v.y : 0.01f * v.y;
                v.z = (v.z >= 0.f) ? v.z : 0.01f * v.z;
                v.w = (v.w >= 0.f) ? v.w : 0.01f * v.w;
            }
        }
        return v;
    };

    // prefetch tile 0
    float4 xv = loadA(koff + xc);
    float4 wv[WCH];
#pragma unroll
    for (int p = 0; p < WCH; p++)
        wv[p] = *(const float4*)&Wp[(koff + wr[p]) * N + n0 + wc[p]];

    As[0][xc + 0][xr] = xv.x; As[0][xc + 1][xr] = xv.y;
    As[0][xc + 2][xr] = xv.z; As[0][xc + 3][xr] = xv.w;
#pragma unroll
    for (int p = 0; p < WCH; p++)
        *(float4*)&Bs[0][wr[p]][wc[p]] = wv[p];
    __syncthreads();

    float acc[2][MNJ];
#pragma unroll
    for (int i = 0; i < 2; i++)
#pragma unroll
        for (int j = 0; j < MNJ; j++) acc[i][j] = 0.f;

#pragma unroll 1
    for (int it = 0; it < NIT; it++) {
        const int cur = it & 1;
        if (it + 1 < NIT) {
            const int k1 = koff + (it + 1) * TK;
            xv = loadA(k1 + xc);
#pragma unroll
            for (int p = 0; p < WCH; p++)
                wv[p] = *(const float4*)&Wp[(k1 + wr[p]) * N + n0 + wc[p]];
        }
#pragma unroll
        for (int k = 0; k < TK; k++) {
            float2 a = *(const float2*)&As[cur][k][ty * 2];
            if (MNJ == 4) {
                float4 b = *(const float4*)&Bs[cur][k][tx * 4];
                acc[0][0] = fmaf(a.x, b.x, acc[0][0]);
                acc[0][1] = fmaf(a.x, b.y, acc[0][1]);
                acc[0][2] = fmaf(a.x, b.z, acc[0][2]);
                acc[0][3] = fmaf(a.x, b.w, acc[0][3]);
                acc[1][0] = fmaf(a.y, b.x, acc[1][0]);
                acc[1][1] = fmaf(a.y, b.y, acc[1][1]);
                acc[1][2] = fmaf(a.y, b.z, acc[1][2]);
                acc[1][3] = fmaf(a.y, b.w, acc[1][3]);
            } else {
                float2 b = *(const float2*)&Bs[cur][k][tx * 2];
                acc[0][0] = fmaf(a.x, b.x, acc[0][0]);
                acc[0][1] = fmaf(a.x, b.y, acc[0][1]);
                acc[1][0] = fmaf(a.y, b.x, acc[1][0]);
                acc[1][1] = fmaf(a.y, b.y, acc[1][1]);
            }
        }
        if (it + 1 < NIT) {
            const int nxt = cur ^ 1;
            As[nxt][xc + 0][xr] = xv.x; As[nxt][xc + 1][xr] = xv.y;
            As[nxt][xc + 2][xr] = xv.z; As[nxt][xc + 3][xr] = xv.w;
#pragma unroll
            for (int p = 0; p < WCH; p++)
                *(float4*)&Bs[nxt][wr[p]][wc[p]] = wv[p];
            __syncthreads();
        }
    }

#pragma unroll
    for (int i = 0; i < 2; i++) {
        int m = m0 + ty * 2 + i;
#pragma unroll
        for (int j = 0; j < MNJ; j++) {
            int n = n0 + tx * MNJ + j;
            float v = acc[i][j];
            if (bp) v += bp[n];
            op[m * N + n] = v;
        }
    }
}

// ---------------------------------------------------------------------------
// Inclusive column prefix-sum over 1024 rows of (in0+in1), fused BN+relu:
//   h = (cumsum + bias) * (g * rsqrt(1+eps)) + bt ; relu
// ---------------------------------------------------------------------------
__global__ void cumsum2_k(const float* __restrict__ in0, const float* __restrict__ in1,
                          float* __restrict__ out,
                          const float* __restrict__ bias, const float* __restrict__ g,
                          const float* __restrict__ bt) {
    const int C = HH;
    const int c = blockIdx.x;
    const int t = threadIdx.x;
    __shared__ float ssum[256];

    float v[4];
    float run = 0.f;
    const int base = t * 4;
#pragma unroll
    for (int r = 0; r < 4; r++) {
        int idx = (base + r) * C + c;
        v[r] = in0[idx] + in1[idx];
        run += v[r];
        v[r] = run;
    }
    ssum[t] = run;
    __syncthreads();
    for (int off = 1; off < 256; off <<= 1) {
        float addv = 0.f;
        if (t >= off) addv = ssum[t - off];
        __syncthreads();
        if (t >= off) ssum[t] += addv;
        __syncthreads();
    }
    float excl = (t > 0) ? ssum[t - 1] : 0.f;
    float sc   = g[c] * rsqrtf(1.f + 1e-5f);
    float bb   = bias[c];
    float btc  = bt[c];
#pragma unroll
    for (int r = 0; r < 4; r++) {
        float h = (v[r] + excl + bb) * sc + btc;
        out[(base + r) * C + c] = fmaxf(h, 0.f);
    }
}

// ---------------------------------------------------------------------------
// Edge kernel: 64x64 pair tile, 256 threads, 4x4 micro stride-16 mapping,
// packed f32x2 math. Inputs are split-K partial pairs (summed at staging).
// p(i,j) = sigmoid(sum_h relu(A[i,h]+B[j,h]) * w[h] + eb2); both halves + diag.
// ---------------------------------------------------------------------------
#define ESA 256
#define ESB 260
#define EDGE_SMEM ((64 * ESA + 64 * ESB + 256) * 4)

__global__ __launch_bounds__(256) void edge_k(
    const float* __restrict__ Aa, const float* __restrict__ Ab,
    const float* __restrict__ Ba, const float* __restrict__ Bb,
    const float* __restrict__ ew2, const float* __restrict__ eb2,
    float* __restrict__ out) {
    const int ti = blockIdx.y, tj = blockIdx.x;
    if (tj < ti) return;

    extern __shared__ float sh[];
    float* As = sh;                       // 64 * 256 (broadcast rows, no pad)
    float* Bs = sh + 64 * ESA;            // 64 * 260
    float* ws = sh + 64 * ESA + 64 * ESB; // 256

    const int t = threadIdx.x;
    ws[t] = ew2[t];

    const int i0 = ti * 64, j0 = tj * 64;
#pragma unroll
    for (int p = 0; p < 16; p++) {
        int q = t + 256 * p;
        int r = q >> 6;
        int c = (q & 63) << 2;
        int gi = (i0 + r) * HH + c;
        int gj = (j0 + r) * HH + c;
        float4 a0 = *(const float4*)&Aa[gi];
        float4 a1 = *(const float4*)&Ab[gi];
        a0.x += a1.x; a0.y += a1.y; a0.z += a1.z; a0.w += a1.w;
        *(float4*)&As[r * ESA + c] = a0;
        float4 b0 = *(const float4*)&Ba[gj];
        float4 b1 = *(const float4*)&Bb[gj];
        b0.x += b1.x; b0.y += b1.y; b0.z += b1.z; b0.w += b1.w;
        *(float4*)&Bs[r * ESB + c] = b0;
    }
    __syncthreads();

    const int tx = t & 15, ty = t >> 4;

    u64 acc[4][4];
#pragma unroll
    for (int di = 0; di < 4; di++)
#pragma unroll
        for (int dj = 0; dj < 4; dj++) acc[di][dj] = 0ull;

#pragma unroll 2
    for (int h = 0; h < HH; h += 4) {
        u64 w01 = *(const u64*)&ws[h];
        u64 w23 = *(const u64*)&ws[h + 2];
        u64 a01[4], a23[4], b01[4], b23[4];
#pragma unroll
        for (int d = 0; d < 4; d++) {
            ulonglong2 av = *(const ulonglong2*)&As[(ty + 16 * d) * ESA + h];
            a01[d] = av.x; a23[d] = av.y;
            ulonglong2 bv = *(const ulonglong2*)&Bs[(tx + 16 * d) * ESB + h];
            b01[d] = bv.x; b23[d] = bv.y;
        }
#pragma unroll
        for (int di = 0; di < 4; di++) {
#pragma unroll
            for (int dj = 0; dj < 4; dj++) {
                acc[di][dj] = fma2(relu2(add2(a01[di], b01[dj])), w01, acc[di][dj]);
                acc[di][dj] = fma2(relu2(add2(a23[di], b23[dj])), w23, acc[di][dj]);
            }
        }
    }

    const float e2 = eb2[0];
#pragma unroll
    for (int di = 0; di < 4; di++) {
#pragma unroll
        for (int dj = 0; dj < 4; dj++) {
            int gi = i0 + ty + 16 * di;
            int gj = j0 + tx + 16 * dj;
            float s = sum2(acc[di][dj]) + e2;
            if (gi < gj) {
                float pv = 1.f / (1.f + __expf(-s));
                out[gi * NN + gj] = pv;
                out[gj * NN + gi] = pv;
            } else if (gi == gj) {
                out[gi * NN + gi] = 0.f;
            }
        }
    }
}

// ---------------------------------------------------------------------------
extern "C" void kernel_launch(void* const* d_in, const int* in_sizes, int n_in,
                              void* d_out, int out_size) {
    (void)in_sizes; (void)n_in; (void)out_size;
    const float* x0  = (const float*)d_in[0];
    const float* w1a = (const float*)d_in[1];
    const float* b1a = (const float*)d_in[2];
    const float* g1  = (const float*)d_in[3];
    const float* bt1 = (const float*)d_in[4];
    const float* w1b = (const float*)d_in[5];
    const float* b1b = (const float*)d_in[6];
    const float* w2a = (const float*)d_in[7];
    const float* b2a = (const float*)d_in[8];
    const float* g2  = (const float*)d_in[9];
    const float* bt2 = (const float*)d_in[10];
    const float* w2b = (const float*)d_in[11];
    const float* b2b = (const float*)d_in[12];
    const float* lw1 = (const float*)d_in[13];
    const float* lb1 = (const float*)d_in[14];
    const float* lw2 = (const float*)d_in[15];
    const float* lb2 = (const float*)d_in[16];
    const float* ew1 = (const float*)d_in[17];
    const float* eb1 = (const float*)d_in[18];
    const float* ew2 = (const float*)d_in[19];
    const float* eb2 = (const float*)d_in[20];
    float* out = (float*)d_out;

    float *S0, *S1, *S2, *S3, *S4, *S5;
    cudaGetSymbolAddress((void**)&S0, g_s0);
    cudaGetSymbolAddress((void**)&S1, g_s1);
    cudaGetSymbolAddress((void**)&S2, g_s2);
    cudaGetSymbolAddress((void**)&S3, g_s3);
    cudaGetSymbolAddress((void**)&S4, g_s4);
    cudaGetSymbolAddress((void**)&S5, g_s5);

    const dim3 blk(256);
    const dim3 gS64(4, 32, 2);   // TN=64, split-K   -> 256 blocks
    const dim3 gS32(4, 32, 2);   // TN=32, split-K   -> 256 blocks
    const dim3 gDS(4, 32, 4);    // dual + split-K   -> 512 blocks

    // G1: x0 @ w1a (split) -> S0,S1 ; cumsum+BN+relu -> S2
    sgemm6<128, 256, 64, 0, 0, 1><<<gS64, blk>>>(x0, nullptr, nullptr, w1a, nullptr, nullptr, S0, S1, nullptr, nullptr);
    cumsum2_k<<<256, blk>>>(S0, S1, S2, b1a, g1, bt1);

    // G2: S2 @ w1b (split, raw) -> S0,S1   [relu+b1b deferred to G3 A-load]
    sgemm6<256, 256, 64, 0, 0, 1><<<gS64, blk>>>(S2, nullptr, nullptr, w1b, nullptr, nullptr, S0, S1, nullptr, nullptr);

    // G3: relu(S0+S1+b1b) @ w2a (split) -> S3,S4 ; cumsum+BN+relu -> S2
    sgemm6<256, 256, 64, 2, 0, 1><<<gS64, blk>>>(S0, S1, b1b, w2a, nullptr, nullptr, S3, S4, nullptr, nullptr);
    cumsum2_k<<<256, blk>>>(S3, S4, S2, b2a, g2, bt2);

    // G4: S2 @ w2b (split, raw) -> S0,S1   [relu+b2b deferred]
    sgemm6<256, 128, 32, 0, 0, 1><<<gS32, blk>>>(S2, nullptr, nullptr, w2b, nullptr, nullptr, S0, S1, nullptr, nullptr);

    // G5: relu(S0+S1+b2b) @ lw1 (split, raw) -> S3,S4   [leaky+lb1 deferred]
    sgemm6<128, 256, 64, 2, 0, 1><<<gS64, blk>>>(S0, S1, b2b, lw1, nullptr, nullptr, S3, S4, nullptr, nullptr);

    // G6: leaky(S3+S4+lb1) @ lw2 + lb2 (split, lb2 in half0) -> S0,S1
    sgemm6<256, 128, 32, 3, 0, 1><<<gS32, blk>>>(S3, S4, lb1, lw2, nullptr, lb2, S0, S1, nullptr, nullptr);

    // G7 (dual+split): (S0+S1) @ ew1_lo + eb1 -> S2,S3 ; @ ew1_hi -> S4,S5
    sgemm6<128, 256, 64, 1, 1, 1><<<gDS, blk>>>(S0, S1, nullptr, ew1, ew1 + 128 * HH, eb1, S2, S3, S4, S5);

    // Pairwise edge probabilities
    (void)cudaFuncSetAttribute(edge_k, cudaFuncAttributeMaxDynamicSharedMemorySize, EDGE_SMEM);
    edge_k<<<dim3(16, 16), blk, EDGE_SMEM>>>(S2, S3, S4, S5, ew2, eb2, out);
}

// round 8
// speedup vs baseline: 1.2496x; 1.0231x over previous
#include <cuda_runtime.h>
#include <cuda_bf16.h>
#include <math.h>

// ---------------------------------------------------------------------------
// N=1024 nodes, F=128, H=256, complete graph.
//  - GIN aggregation on triu edges == inclusive prefix-sum over rows.
//  - cumsum(X) @ W == cumsum(X @ W)  -> GEMM first, scan after.
//  - leaky(relu(z)) == relu(z).
//  - Edge MLP: hidden = A[src] + B[dst], A = x@ew1[:F]+eb1, B = x@ew1[F:].
// R8 = R7 with valid relu (no max.f32x2 in PTX; use FMNMX pair on alu pipe).
// ---------------------------------------------------------------------------

#define NN 1024
#define HH 256

__device__ float g_buf1[NN * HH];
__device__ float g_buf2[NN * HH];
__device__ float g_A[NN * HH];
__device__ float g_B[NN * HH];

typedef unsigned long long u64;

// ---- packed f32x2 helpers (sm_100a) ---------------------------------------
__device__ __forceinline__ u64 add2(u64 a, u64 b) {
    u64 r; asm("add.rn.f32x2 %0, %1, %2;" : "=l"(r) : "l"(a), "l"(b)); return r;
}
__device__ __forceinline__ u64 fma2(u64 a, u64 b, u64 c) {
    u64 r; asm("fma.rn.f32x2 %0, %1, %2, %3;" : "=l"(r) : "l"(a), "l"(b), "l"(c)); return r;
}
__device__ __forceinline__ u64 relu2(u64 t) {
    unsigned lo, hi;
    asm("mov.b64 {%0, %1}, %2;" : "=r"(lo), "=r"(hi) : "l"(t));
    float flo = fmaxf(__uint_as_float(lo), 0.f);
    float fhi = fmaxf(__uint_as_float(hi), 0.f);
    u64 r;
    asm("mov.b64 %0, {%1, %2};" : "=l"(r)
        : "r"(__float_as_uint(flo)), "r"(__float_as_uint(fhi)));
    return r;
}
__device__ __forceinline__ float sum2(u64 t) {
    unsigned lo, hi;
    asm("mov.b64 {%0, %1}, %2;" : "=r"(lo), "=r"(hi) : "l"(t));
    return __uint_as_float(lo) + __uint_as_float(hi);
}

// ---------------------------------------------------------------------------
// GEMM v7: out[M,N] = X[M,K] @ W[K,N] (+bias)(+epilogue), 128 threads/CTA.
// (TM,TN) = (16,64) for N=256 -> 256 CTAs; (32,32) for N=128 -> 128 CTAs.
// Micro 2x4 per thread (8 FMA per 24B of LDS) — R4-proven intensity.
// Double-buffered smem + register prefetch, one sync per K-iteration.
// DUAL: blockIdx.z==1 computes X @ W2 -> out2 (no bias) in the same launch.
// EPI: 0=none, 1=relu, 2=leaky(0.01)
// ---------------------------------------------------------------------------
template <int K, int N, int TM, int TN, int EPI, int DUAL>
__global__ __launch_bounds__(128) void sgemm7(
    const float* __restrict__ X, const float* __restrict__ W,
    const float* __restrict__ W2, const float* __restrict__ bias,
    float* __restrict__ out, float* __restrict__ out2) {

    constexpr int TK  = 32;
    constexpr int NIT = K / TK;
    constexpr int ACH = TM / 16;                 // A float4 chunks per thread
    constexpr int WCH = TN / 16;                 // W float4 chunks per thread
    constexpr int TC  = TN / 4;                  // thread cols

    __shared__ float As[2][TK][TM + 2];
    __shared__ float Bs[2][TK][TN];

    const int t  = threadIdx.x;
    const int tx = t % TC;
    const int ty = t / TC;
    const int m0 = blockIdx.y * TM;
    const int n0 = blockIdx.x * TN;

    const float* Wp = W;
    const float* bp = bias;
    float*       op = out;
    if (DUAL && blockIdx.z) { Wp = W2; bp = nullptr; op = out2; }

    int ar[ACH], ac[ACH], wr[WCH], wc[WCH];
#pragma unroll
    for (int p = 0; p < ACH; p++) {
        int q = t + 128 * p;
        ar[p] = q >> 3;
        ac[p] = (q & 7) * 4;
    }
#pragma unroll
    for (int p = 0; p < WCH; p++) {
        int q = (t + 128 * p) * 4;
        wr[p] = q / TN;
        wc[p] = q % TN;
    }

    // prefetch tile 0
    float4 xv[ACH], wv[WCH];
#pragma unroll
    for (int p = 0; p < ACH; p++)
        xv[p] = *(const float4*)&X[(m0 + ar[p]) * K + ac[p]];
#pragma unroll
    for (int p = 0; p < WCH; p++)
        wv[p] = *(const float4*)&Wp[wr[p] * N + n0 + wc[p]];

#pragma unroll
    for (int p = 0; p < ACH; p++) {
        As[0][ac[p] + 0][ar[p]] = xv[p].x; As[0][ac[p] + 1][ar[p]] = xv[p].y;
        As[0][ac[p] + 2][ar[p]] = xv[p].z; As[0][ac[p] + 3][ar[p]] = xv[p].w;
    }
#pragma unroll
    for (int p = 0; p < WCH; p++)
        *(float4*)&Bs[0][wr[p]][wc[p]] = wv[p];
    __syncthreads();

    float acc[2][4];
#pragma unroll
    for (int i = 0; i < 2; i++)
#pragma unroll
        for (int j = 0; j < 4; j++) acc[i][j] = 0.f;

#pragma unroll 1
    for (int it = 0; it < NIT; it++) {
        const int cur = it & 1;
        if (it + 1 < NIT) {
            const int k1 = (it + 1) * TK;
#pragma unroll
            for (int p = 0; p < ACH; p++)
                xv[p] = *(const float4*)&X[(m0 + ar[p]) * K + k1 + ac[p]];
#pragma unroll
            for (int p = 0; p < WCH; p++)
                wv[p] = *(const float4*)&Wp[(k1 + wr[p]) * N + n0 + wc[p]];
        }
#pragma unroll
        for (int k = 0; k < TK; k++) {
            float2 a = *(const float2*)&As[cur][k][ty * 2];
            float4 b = *(const float4*)&Bs[cur][k][tx * 4];
            acc[0][0] = fmaf(a.x, b.x, acc[0][0]);
            acc[0][1] = fmaf(a.x, b.y, acc[0][1]);
            acc[0][2] = fmaf(a.x, b.z, acc[0][2]);
            acc[0][3] = fmaf(a.x, b.w, acc[0][3]);
            acc[1][0] = fmaf(a.y, b.x, acc[1][0]);
            acc[1][1] = fmaf(a.y, b.y, acc[1][1]);
            acc[1][2] = fmaf(a.y, b.z, acc[1][2]);
            acc[1][3] = fmaf(a.y, b.w, acc[1][3]);
        }
        if (it + 1 < NIT) {
            const int nxt = cur ^ 1;
#pragma unroll
            for (int p = 0; p < ACH; p++) {
                As[nxt][ac[p] + 0][ar[p]] = xv[p].x; As[nxt][ac[p] + 1][ar[p]] = xv[p].y;
                As[nxt][ac[p] + 2][ar[p]] = xv[p].z; As[nxt][ac[p] + 3][ar[p]] = xv[p].w;
            }
#pragma unroll
            for (int p = 0; p < WCH; p++)
                *(float4*)&Bs[nxt][wr[p]][wc[p]] = wv[p];
            __syncthreads();
        }
    }

#pragma unroll
    for (int i = 0; i < 2; i++) {
        int m = m0 + ty * 2 + i;
#pragma unroll
        for (int j = 0; j < 4; j++) {
            int n = n0 + tx * 4 + j;
            float v = acc[i][j];
            if (bp) v += bp[n];
            if (EPI == 1) v = fmaxf(v, 0.f);
            if (EPI == 2) v = (v >= 0.f) ? v : 0.01f * v;
            op[m * N + n] = v;
        }
    }
}

// ---------------------------------------------------------------------------
// Inclusive column prefix-sum over 1024 rows (256 cols), fused BN+relu:
//   h = (cumsum + bias) * (g * rsqrt(1+eps)) + bt ; relu
// ---------------------------------------------------------------------------
__global__ void cumsum_bn_relu_k(const float* __restrict__ in, float* __restrict__ out,
                                 const float* __restrict__ bias, const float* __restrict__ g,
                                 const float* __restrict__ bt) {
    const int C = HH;
    const int c = blockIdx.x;
    const int t = threadIdx.x;
    __shared__ float ssum[256];

    float v[4];
    float run = 0.f;
    const int base = t * 4;
#pragma unroll
    for (int r = 0; r < 4; r++) {
        v[r] = in[(base + r) * C + c];
        run += v[r];
        v[r] = run;
    }
    ssum[t] = run;
    __syncthreads();
    for (int off = 1; off < 256; off <<= 1) {
        float addv = 0.f;
        if (t >= off) addv = ssum[t - off];
        __syncthreads();
        if (t >= off) ssum[t] += addv;
        __syncthreads();
    }
    float excl = (t > 0) ? ssum[t - 1] : 0.f;
    float sc   = g[c] * rsqrtf(1.f + 1e-5f);
    float bb   = bias[c];
    float btc  = bt[c];
#pragma unroll
    for (int r = 0; r < 4; r++) {
        float h = (v[r] + excl + bb) * sc + btc;
        out[(base + r) * C + c] = fmaxf(h, 0.f);
    }
}

// ---------------------------------------------------------------------------
// Edge kernel: 64x64 pair tile, 256 threads, 4x4 micro stride-16 mapping,
// packed f32x2 add/fma + FMNMX-pair relu.
// p(i,j) = sigmoid(sum_h relu(A[i,h]+B[j,h]) * w[h] + eb2); both halves + diag.
// ---------------------------------------------------------------------------
#define ESA 256
#define ESB 260
#define EDGE_SMEM ((64 * ESA + 64 * ESB + 256) * 4)

__global__ __launch_bounds__(256) void edge_k(
    const float* __restrict__ A, const float* __restrict__ Bm,
    const float* __restrict__ ew2, const float* __restrict__ eb2,
    float* __restrict__ out) {
    const int ti = blockIdx.y, tj = blockIdx.x;
    if (tj < ti) return;

    extern __shared__ float sh[];
    float* As = sh;                       // 64 * 256 (broadcast rows, no pad)
    float* Bs = sh + 64 * ESA;            // 64 * 260
    float* ws = sh + 64 * ESA + 64 * ESB; // 256

    const int t = threadIdx.x;
    ws[t] = ew2[t];

    const int i0 = ti * 64, j0 = tj * 64;
#pragma unroll
    for (int p = 0; p < 16; p++) {
        int q = t + 256 * p;
        int r = q >> 6;
        int c = (q & 63) << 2;
        *(float4*)&As[r * ESA + c] = *(const float4*)&A[(i0 + r) * HH + c];
        *(float4*)&Bs[r * ESB + c] = *(const float4*)&Bm[(j0 + r) * HH + c];
    }
    __syncthreads();

    const int tx = t & 15, ty = t >> 4;

    u64 acc[4][4];
#pragma unroll
    for (int di = 0; di < 4; di++)
#pragma unroll
        for (int dj = 0; dj < 4; dj++) acc[di][dj] = 0ull;

#pragma unroll 2
    for (int h = 0; h < HH; h += 4) {
        u64 w01 = *(const u64*)&ws[h];
        u64 w23 = *(const u64*)&ws[h + 2];
        u64 a01[4], a23[4], b01[4], b23[4];
#pragma unroll
        for (int d = 0; d < 4; d++) {
            ulonglong2 av = *(const ulonglong2*)&As[(ty + 16 * d) * ESA + h];
            a01[d] = av.x; a23[d] = av.y;
            ulonglong2 bv = *(const ulonglong2*)&Bs[(tx + 16 * d) * ESB + h];
            b01[d] = bv.x; b23[d] = bv.y;
        }
#pragma unroll
        for (int di = 0; di < 4; di++) {
#pragma unroll
            for (int dj = 0; dj < 4; dj++) {
                acc[di][dj] = fma2(relu2(add2(a01[di], b01[dj])), w01, acc[di][dj]);
                acc[di][dj] = fma2(relu2(add2(a23[di], b23[dj])), w23, acc[di][dj]);
            }
        }
    }

    const float e2 = eb2[0];
#pragma unroll
    for (int di = 0; di < 4; di++) {
#pragma unroll
        for (int dj = 0; dj < 4; dj++) {
            int gi = i0 + ty + 16 * di;
            int gj = j0 + tx + 16 * dj;
            float s = sum2(acc[di][dj]) + e2;
            if (gi < gj) {
                float pv = 1.f / (1.f + __expf(-s));
                out[gi * NN + gj] = pv;
                out[gj * NN + gi] = pv;
            } else if (gi == gj) {
                out[gi * NN + gi] = 0.f;
            }
        }
    }
}

// ---------------------------------------------------------------------------
extern "C" void kernel_launch(void* const* d_in, const int* in_sizes, int n_in,
                              void* d_out, int out_size) {
    (void)in_sizes; (void)n_in; (void)out_size;
    const float* x0  = (const float*)d_in[0];
    const float* w1a = (const float*)d_in[1];
    const float* b1a = (const float*)d_in[2];
    const float* g1  = (const float*)d_in[3];
    const float* bt1 = (const float*)d_in[4];
    const float* w1b = (const float*)d_in[5];
    const float* b1b = (const float*)d_in[6];
    const float* w2a = (const float*)d_in[7];
    const float* b2a = (const float*)d_in[8];
    const float* g2  = (const float*)d_in[9];
    const float* bt2 = (const float*)d_in[10];
    const float* w2b = (const float*)d_in[11];
    const float* b2b = (const float*)d_in[12];
    const float* lw1 = (const float*)d_in[13];
    const float* lb1 = (const float*)d_in[14];
    const float* lw2 = (const float*)d_in[15];
    const float* lb2 = (const float*)d_in[16];
    const float* ew1 = (const float*)d_in[17];
    const float* eb1 = (const float*)d_in[18];
    const float* ew2 = (const float*)d_in[19];
    const float* eb2 = (const float*)d_in[20];
    float* out = (float*)d_out;

    float *B1, *B2, *Ap, *Bp;
    cudaGetSymbolAddress((void**)&B1, g_buf1);
    cudaGetSymbolAddress((void**)&B2, g_buf2);
    cudaGetSymbolAddress((void**)&Ap, g_A);
    cudaGetSymbolAddress((void**)&Bp, g_B);

    const dim3 blk(128);
    const dim3 gA(4, 64);        // N=256: TM16/TN64 -> 256 CTAs
    const dim3 gB(4, 32);        // N=128: TM32/TN32 -> 128 CTAs
    const dim3 gD(4, 64, 2);     // dual edge GEMM  -> 512 CTAs

    // GIN layer 1
    sgemm7<128, 256, 16, 64, 0, 0><<<gA, blk>>>(x0, w1a, nullptr, nullptr, B1, nullptr);
    cumsum_bn_relu_k<<<256, 256>>>(B1, B2, b1a, g1, bt1);
    sgemm7<256, 256, 16, 64, 1, 0><<<gA, blk>>>(B2, w1b, nullptr, b1b, B1, nullptr);

    // GIN layer 2
    sgemm7<256, 256, 16, 64, 0, 0><<<gA, blk>>>(B1, w2a, nullptr, nullptr, B2, nullptr);
    cumsum_bn_relu_k<<<256, 256>>>(B2, B1, b2a, g2, bt2);
    sgemm7<256, 128, 32, 32, 1, 0><<<gB, blk>>>(B1, w2b, nullptr, b2b, B2, nullptr);

    // Linear head
    sgemm7<128, 256, 16, 64, 2, 0><<<gA, blk>>>(B2, lw1, nullptr, lb1, B1, nullptr);
    sgemm7<256, 128, 32, 32, 0, 0><<<gB, blk>>>(B1, lw2, nullptr, lb2, B2, nullptr);

    // Edge halves in one launch: A = x@ew1[:128]+eb1 ; B = x@ew1[128:]
    sgemm7<128, 256, 16, 64, 0, 1><<<gD, blk>>>(B2, ew1, ew1 + 128 * HH, eb1, Ap, Bp);

    // Pairwise edge probabilities
    (void)cudaFuncSetAttribute(edge_k, cudaFuncAttributeMaxDynamicSharedMemorySize, EDGE_SMEM);
    edge_k<<<dim3(16, 16), dim3(256), EDGE_SMEM>>>(Ap, Bp, ew2, eb2, out);
}

// round 10
// speedup vs baseline: 1.4091x; 1.1277x over previous
#include <cuda_runtime.h>
#include <cuda_bf16.h>
#include <math.h>

// ---------------------------------------------------------------------------
// N=1024 nodes, F=128, H=256, complete graph.
//  - GIN aggregation on triu edges == inclusive prefix-sum over rows.
//  - cumsum(X) @ W == cumsum(X @ W)  -> GEMM first, scan after.
//  - leaky(relu(z)) == relu(z).
//  - Edge MLP: hidden = A[src] + B[dst], A = x@ew1[:F]+eb1, B = x@ew1[F:].
// R10 = R9 (4-stage cp.async pipeline, R4 tile geometry) with stage buffers
//       in DYNAMIC shared memory (static 48KB ceiling broke R9).
// ---------------------------------------------------------------------------

#define NN 1024
#define HH 256

__device__ float g_buf1[NN * HH];
__device__ float g_buf2[NN * HH];
__device__ float g_A[NN * HH];
__device__ float g_B[NN * HH];

typedef unsigned long long u64;

// ---- packed f32x2 helpers (sm_100a) ---------------------------------------
__device__ __forceinline__ u64 add2(u64 a, u64 b) {
    u64 r; asm("add.rn.f32x2 %0, %1, %2;" : "=l"(r) : "l"(a), "l"(b)); return r;
}
__device__ __forceinline__ u64 fma2(u64 a, u64 b, u64 c) {
    u64 r; asm("fma.rn.f32x2 %0, %1, %2, %3;" : "=l"(r) : "l"(a), "l"(b), "l"(c)); return r;
}
__device__ __forceinline__ u64 relu2(u64 t) {
    unsigned lo, hi;
    asm("mov.b64 {%0, %1}, %2;" : "=r"(lo), "=r"(hi) : "l"(t));
    float flo = fmaxf(__uint_as_float(lo), 0.f);
    float fhi = fmaxf(__uint_as_float(hi), 0.f);
    u64 r;
    asm("mov.b64 %0, {%1, %2};" : "=l"(r)
        : "r"(__float_as_uint(flo)), "r"(__float_as_uint(fhi)));
    return r;
}
__device__ __forceinline__ float sum2(u64 t) {
    unsigned lo, hi;
    asm("mov.b64 {%0, %1}, %2;" : "=r"(lo), "=r"(hi) : "l"(t));
    return __uint_as_float(lo) + __uint_as_float(hi);
}

// ---- cp.async helpers ------------------------------------------------------
__device__ __forceinline__ void cpa16(unsigned dst, const void* src) {
    asm volatile("cp.async.cg.shared.global [%0], [%1], 16;" :: "r"(dst), "l"(src));
}
#define CPA_COMMIT() asm volatile("cp.async.commit_group;")
#define CPA_WAIT2()  asm volatile("cp.async.wait_group 2;")

// ---------------------------------------------------------------------------
// GEMM v10: out[M,N] = X[M,K] @ W[K,N] (+bias)(+epilogue), 256 threads.
// TM=32, TN in {64,32}, TK=32, 2x(TN/16) micro. 4-stage cp.async pipeline in
// dynamic smem: prologue commits tiles 0..2; iter it: wait_group 2 -> bar ->
// compute stage it%4 -> issue tile it+3 -> commit. A staged m-major.
// DUAL: blockIdx.z==1 computes X @ W2 -> out2 (no bias) in the same launch.
// EPI: 0=none, 1=relu, 2=leaky(0.01)
// ---------------------------------------------------------------------------
#define GAP 36                                   // A row pitch (floats)
#define GNS 4                                    // pipeline stages

template <int K, int N, int TN, int EPI, int DUAL>
__global__ __launch_bounds__(256) void sgemm10(
    const float* __restrict__ X, const float* __restrict__ W,
    const float* __restrict__ W2, const float* __restrict__ bias,
    float* __restrict__ out, float* __restrict__ out2) {

    constexpr int TK  = 32;
    constexpr int NIT = K / TK;                   // 4 or 8
    constexpr int MNJ = TN / 16;                  // 4 or 2 cols per thread
    constexpr int WCH = TN / 32;                  // B 16B chunks per thread

    extern __shared__ float sh[];
    float* Asm = sh;                              // GNS*32*GAP
    float* Bsm = sh + GNS * 32 * GAP;             // GNS*TK*TN

    const int t  = threadIdx.x;
    const int tx = t & 15;
    const int ty = t >> 4;
    const int m0 = blockIdx.y * 32;
    const int n0 = blockIdx.x * TN;

    const float* Wp = W;
    const float* bp = bias;
    float*       op = out;
    if (DUAL && blockIdx.z) { Wp = W2; bp = nullptr; op = out2; }

    // A chunk: 32m x 32k = 4KB = 256 x 16B -> one per thread
    const int am  = t >> 3;                       // 0..31
    const int akc = (t & 7) * 4;                  // k offset
    // B chunks
    int br[WCH > 0 ? WCH : 1], bc[WCH > 0 ? WCH : 1];
#pragma unroll
    for (int p = 0; p < WCH; p++) {
        int q = (t + 256 * p);
        br[p] = q / (TN / 4);
        bc[p] = (q % (TN / 4)) * 4;
    }

    unsigned aSh = (unsigned)__cvta_generic_to_shared(Asm);
    unsigned bSh = (unsigned)__cvta_generic_to_shared(Bsm);

    auto issueTile = [&](int tile) {
        const int s  = tile & (GNS - 1);
        const int k0 = tile * TK;
        cpa16(aSh + (unsigned)(((s * 32 + am) * GAP + akc) * 4),
              &X[(m0 + am) * K + k0 + akc]);
#pragma unroll
        for (int p = 0; p < WCH; p++)
            cpa16(bSh + (unsigned)(((s * TK + br[p]) * TN + bc[p]) * 4),
                  &Wp[(k0 + br[p]) * N + n0 + bc[p]]);
    };

#pragma unroll
    for (int s = 0; s < GNS - 1; s++) { issueTile(s); CPA_COMMIT(); }

    float acc[2][MNJ];
#pragma unroll
    for (int i = 0; i < 2; i++)
#pragma unroll
        for (int j = 0; j < MNJ; j++) acc[i][j] = 0.f;

#pragma unroll 1
    for (int it = 0; it < NIT; it++) {
        const int s = it & (GNS - 1);
        CPA_WAIT2();
        __syncthreads();
        const float* Ar0 = &Asm[(s * 32 + ty * 2 + 0) * GAP];
        const float* Ar1 = &Asm[(s * 32 + ty * 2 + 1) * GAP];
        const float* Bk  = &Bsm[s * TK * TN];
#pragma unroll
        for (int k = 0; k < TK; k++) {
            float a0 = Ar0[k];
            float a1 = Ar1[k];
            if (MNJ == 4) {
                float4 b = *(const float4*)&Bk[k * TN + tx * 4];
                acc[0][0] = fmaf(a0, b.x, acc[0][0]);
                acc[0][1] = fmaf(a0, b.y, acc[0][1]);
                acc[0][2] = fmaf(a0, b.z, acc[0][2]);
                acc[0][3] = fmaf(a0, b.w, acc[0][3]);
                acc[1][0] = fmaf(a1, b.x, acc[1][0]);
                acc[1][1] = fmaf(a1, b.y, acc[1][1]);
                acc[1][2] = fmaf(a1, b.z, acc[1][2]);
                acc[1][3] = fmaf(a1, b.w, acc[1][3]);
            } else {
                float2 b = *(const float2*)&Bk[k * TN + tx * 2];
                acc[0][0] = fmaf(a0, b.x, acc[0][0]);
                acc[0][1] = fmaf(a0, b.y, acc[0][1]);
                acc[1][0] = fmaf(a1, b.x, acc[1][0]);
                acc[1][1] = fmaf(a1, b.y, acc[1][1]);
            }
        }
        if (it + GNS - 1 < NIT) issueTile(it + GNS - 1);
        CPA_COMMIT();
    }

#pragma unroll
    for (int i = 0; i < 2; i++) {
        int m = m0 + ty * 2 + i;
#pragma unroll
        for (int j = 0; j < MNJ; j++) {
            int n = n0 + tx * MNJ + j;
            float v = acc[i][j];
            if (bp) v += bp[n];
            if (EPI == 1) v = fmaxf(v, 0.f);
            if (EPI == 2) v = (v >= 0.f) ? v : 0.01f * v;
            op[m * N + n] = v;
        }
    }
}

#define GEMM_SMEM(TN) ((GNS * 32 * GAP + GNS * 32 * (TN)) * 4)

// ---------------------------------------------------------------------------
// Inclusive column prefix-sum over 1024 rows (256 cols), fused BN+relu:
//   h = (cumsum + bias) * (g * rsqrt(1+eps)) + bt ; relu
// ---------------------------------------------------------------------------
__global__ void cumsum_bn_relu_k(const float* __restrict__ in, float* __restrict__ out,
                                 const float* __restrict__ bias, const float* __restrict__ g,
                                 const float* __restrict__ bt) {
    const int C = HH;
    const int c = blockIdx.x;
    const int t = threadIdx.x;
    __shared__ float ssum[256];

    float v[4];
    float run = 0.f;
    const int base = t * 4;
#pragma unroll
    for (int r = 0; r < 4; r++) {
        v[r] = in[(base + r) * C + c];
        run += v[r];
        v[r] = run;
    }
    ssum[t] = run;
    __syncthreads();
    for (int off = 1; off < 256; off <<= 1) {
        float addv = 0.f;
        if (t >= off) addv = ssum[t - off];
        __syncthreads();
        if (t >= off) ssum[t] += addv;
        __syncthreads();
    }
    float excl = (t > 0) ? ssum[t - 1] : 0.f;
    float sc   = g[c] * rsqrtf(1.f + 1e-5f);
    float bb   = bias[c];
    float btc  = bt[c];
#pragma unroll
    for (int r = 0; r < 4; r++) {
        float h = (v[r] + excl + bb) * sc + btc;
        out[(base + r) * C + c] = fmaxf(h, 0.f);
    }
}

// ---------------------------------------------------------------------------
// Edge kernel: 64x64 pair tile, 256 threads, 4x4 micro stride-16 mapping,
// packed f32x2 add/fma + FMNMX-pair relu.
// p(i,j) = sigmoid(sum_h relu(A[i,h]+B[j,h]) * w[h] + eb2); both halves + diag.
// ---------------------------------------------------------------------------
#define ESA 256
#define ESB 260
#define EDGE_SMEM ((64 * ESA + 64 * ESB + 256) * 4)

__global__ __launch_bounds__(256) void edge_k(
    const float* __restrict__ A, const float* __restrict__ Bm,
    const float* __restrict__ ew2, const float* __restrict__ eb2,
    float* __restrict__ out) {
    const int ti = blockIdx.y, tj = blockIdx.x;
    if (tj < ti) return;

    extern __shared__ float sh[];
    float* As = sh;                       // 64 * 256 (broadcast rows, no pad)
    float* Bs = sh + 64 * ESA;            // 64 * 260
    float* ws = sh + 64 * ESA + 64 * ESB; // 256

    const int t = threadIdx.x;
    ws[t] = ew2[t];

    const int i0 = ti * 64, j0 = tj * 64;
#pragma unroll
    for (int p = 0; p < 16; p++) {
        int q = t + 256 * p;
        int r = q >> 6;
        int c = (q & 63) << 2;
        *(float4*)&As[r * ESA + c] = *(const float4*)&A[(i0 + r) * HH + c];
        *(float4*)&Bs[r * ESB + c] = *(const float4*)&Bm[(j0 + r) * HH + c];
    }
    __syncthreads();

    const int tx = t & 15, ty = t >> 4;

    u64 acc[4][4];
#pragma unroll
    for (int di = 0; di < 4; di++)
#pragma unroll
        for (int dj = 0; dj < 4; dj++) acc[di][dj] = 0ull;

#pragma unroll 2
    for (int h = 0; h < HH; h += 4) {
        u64 w01 = *(const u64*)&ws[h];
        u64 w23 = *(const u64*)&ws[h + 2];
        u64 a01[4], a23[4], b01[4], b23[4];
#pragma unroll
        for (int d = 0; d < 4; d++) {
            ulonglong2 av = *(const ulonglong2*)&As[(ty + 16 * d) * ESA + h];
            a01[d] = av.x; a23[d] = av.y;
            ulonglong2 bv = *(const ulonglong2*)&Bs[(tx + 16 * d) * ESB + h];
            b01[d] = bv.x; b23[d] = bv.y;
        }
#pragma unroll
        for (int di = 0; di < 4; di++) {
#pragma unroll
            for (int dj = 0; dj < 4; dj++) {
                acc[di][dj] = fma2(relu2(add2(a01[di], b01[dj])), w01, acc[di][dj]);
                acc[di][dj] = fma2(relu2(add2(a23[di], b23[dj])), w23, acc[di][dj]);
            }
        }
    }

    const float e2 = eb2[0];
#pragma unroll
    for (int di = 0; di < 4; di++) {
#pragma unroll
        for (int dj = 0; dj < 4; dj++) {
            int gi = i0 + ty + 16 * di;
            int gj = j0 + tx + 16 * dj;
            float s = sum2(acc[di][dj]) + e2;
            if (gi < gj) {
                float pv = 1.f / (1.f + __expf(-s));
                out[gi * NN + gj] = pv;
                out[gj * NN + gi] = pv;
            } else if (gi == gj) {
                out[gi * NN + gi] = 0.f;
            }
        }
    }
}

// ---------------------------------------------------------------------------
extern "C" void kernel_launch(void* const* d_in, const int* in_sizes, int n_in,
                              void* d_out, int out_size) {
    (void)in_sizes; (void)n_in; (void)out_size;
    const float* x0  = (const float*)d_in[0];
    const float* w1a = (const float*)d_in[1];
    const float* b1a = (const float*)d_in[2];
    const float* g1  = (const float*)d_in[3];
    const float* bt1 = (const float*)d_in[4];
    const float* w1b = (const float*)d_in[5];
    const float* b1b = (const float*)d_in[6];
    const float* w2a = (const float*)d_in[7];
    const float* b2a = (const float*)d_in[8];
    const float* g2  = (const float*)d_in[9];
    const float* bt2 = (const float*)d_in[10];
    const float* w2b = (const float*)d_in[11];
    const float* b2b = (const float*)d_in[12];
    const float* lw1 = (const float*)d_in[13];
    const float* lb1 = (const float*)d_in[14];
    const float* lw2 = (const float*)d_in[15];
    const float* lb2 = (const float*)d_in[16];
    const float* ew1 = (const float*)d_in[17];
    const float* eb1 = (const float*)d_in[18];
    const float* ew2 = (const float*)d_in[19];
    const float* eb2 = (const float*)d_in[20];
    float* out = (float*)d_out;

    float *B1, *B2, *Ap, *Bp;
    cudaGetSymbolAddress((void**)&B1, g_buf1);
    cudaGetSymbolAddress((void**)&B2, g_buf2);
    cudaGetSymbolAddress((void**)&Ap, g_A);
    cudaGetSymbolAddress((void**)&Bp, g_B);

    const dim3 blk(256);
    const dim3 gA(4, 32);        // N=256, TN=64 -> 128 blocks
    const dim3 gB(4, 32);        // N=128, TN=32 -> 128 blocks
    const dim3 gD(4, 32, 2);     // dual edge GEMM -> 256 blocks
    const int s64 = GEMM_SMEM(64);
    const int s32 = GEMM_SMEM(32);

    // Raise dynamic smem limits (idempotent; host-side, capture-safe)
    (void)cudaFuncSetAttribute(sgemm10<128, 256, 64, 0, 0>, cudaFuncAttributeMaxDynamicSharedMemorySize, s64);
    (void)cudaFuncSetAttribute(sgemm10<256, 256, 64, 1, 0>, cudaFuncAttributeMaxDynamicSharedMemorySize, s64);
    (void)cudaFuncSetAttribute(sgemm10<256, 256, 64, 0, 0>, cudaFuncAttributeMaxDynamicSharedMemorySize, s64);
    (void)cudaFuncSetAttribute(sgemm10<256, 128, 32, 1, 0>, cudaFuncAttributeMaxDynamicSharedMemorySize, s32);
    (void)cudaFuncSetAttribute(sgemm10<128, 256, 64, 2, 0>, cudaFuncAttributeMaxDynamicSharedMemorySize, s64);
    (void)cudaFuncSetAttribute(sgemm10<256, 128, 32, 0, 0>, cudaFuncAttributeMaxDynamicSharedMemorySize, s32);
    (void)cudaFuncSetAttribute(sgemm10<128, 256, 64, 0, 1>, cudaFuncAttributeMaxDynamicSharedMemorySize, s64);
    (void)cudaFuncSetAttribute(edge_k, cudaFuncAttributeMaxDynamicSharedMemorySize, EDGE_SMEM);

    // GIN layer 1
    sgemm10<128, 256, 64, 0, 0><<<gA, blk, s64>>>(x0, w1a, nullptr, nullptr, B1, nullptr);
    cumsum_bn_relu_k<<<256, 256>>>(B1, B2, b1a, g1, bt1);
    sgemm10<256, 256, 64, 1, 0><<<gA, blk, s64>>>(B2, w1b, nullptr, b1b, B1, nullptr);

    // GIN layer 2
    sgemm10<256, 256, 64, 0, 0><<<gA, blk, s64>>>(B1, w2a, nullptr, nullptr, B2, nullptr);
    cumsum_bn_relu_k<<<256, 256>>>(B2, B1, b2a, g2, bt2);
    sgemm10<256, 128, 32, 1, 0><<<gB, blk, s32>>>(B1, w2b, nullptr, b2b, B2, nullptr);

    // Linear head
    sgemm10<128, 256, 64, 2, 0><<<gA, blk, s64>>>(B2, lw1, nullptr, lb1, B1, nullptr);
    sgemm10<256, 128, 32, 0, 0><<<gB, blk, s32>>>(B1, lw2, nullptr, lb2, B2, nullptr);

    // Edge halves in one launch: A = x@ew1[:128]+eb1 ; B = x@ew1[128:]
    sgemm10<128, 256, 64, 0, 1><<<gD, blk, s64>>>(B2, ew1, ew1 + 128 * HH, eb1, Ap, Bp);

    // Pairwise edge probabilities
    edge_k<<<dim3(16, 16), dim3(256), EDGE_SMEM>>>(Ap, Bp, ew2, eb2, out);
}

// round 12
// speedup vs baseline: 1.4097x; 1.0004x over previous
#include <cuda_runtime.h>
#include <cuda_bf16.h>
#include <math.h>

// ---------------------------------------------------------------------------
// N=1024 nodes, F=128, H=256, complete graph.
//  - GIN aggregation on triu edges == inclusive prefix-sum over rows.
//  - cumsum(X) @ W == cumsum(X @ W)  -> GEMM first, scan after.
//  - leaky(relu(z)) == relu(z).
//  - Edge MLP: hidden = A[src] + B[dst], A = x@ew1[:F]+eb1, B = x@ew1[F:].
// R12 = R11 resubmit (infra flake): GEMM mainloop in packed f32x2 (FFMA2,
//       IEEE-exact), vectorized A reads; edge kernel retiled 64x32.
// ---------------------------------------------------------------------------

#define NN 1024
#define HH 256

__device__ float g_buf1[NN * HH];
__device__ float g_buf2[NN * HH];
__device__ float g_A[NN * HH];
__device__ float g_B[NN * HH];

typedef unsigned long long u64;

// ---- packed f32x2 helpers (sm_100a) ---------------------------------------
__device__ __forceinline__ u64 add2(u64 a, u64 b) {
    u64 r; asm("add.rn.f32x2 %0, %1, %2;" : "=l"(r) : "l"(a), "l"(b)); return r;
}
__device__ __forceinline__ u64 fma2(u64 a, u64 b, u64 c) {
    u64 r; asm("fma.rn.f32x2 %0, %1, %2, %3;" : "=l"(r) : "l"(a), "l"(b), "l"(c)); return r;
}
__device__ __forceinline__ u64 relu2(u64 t) {
    unsigned lo, hi;
    asm("mov.b64 {%0, %1}, %2;" : "=r"(lo), "=r"(hi) : "l"(t));
    float flo = fmaxf(__uint_as_float(lo), 0.f);
    float fhi = fmaxf(__uint_as_float(hi), 0.f);
    u64 r;
    asm("mov.b64 %0, {%1, %2};" : "=l"(r)
        : "r"(__float_as_uint(flo)), "r"(__float_as_uint(fhi)));
    return r;
}
__device__ __forceinline__ float sum2(u64 t) {
    unsigned lo, hi;
    asm("mov.b64 {%0, %1}, %2;" : "=r"(lo), "=r"(hi) : "l"(t));
    return __uint_as_float(lo) + __uint_as_float(hi);
}
__device__ __forceinline__ u64 dup2(float a) {
    u64 r; unsigned u = __float_as_uint(a);
    asm("mov.b64 %0, {%1, %1};" : "=l"(r) : "r"(u));
    return r;
}
__device__ __forceinline__ void unpack2(u64 t, float& lo, float& hi) {
    unsigned a, b;
    asm("mov.b64 {%0, %1}, %2;" : "=r"(a), "=r"(b) : "l"(t));
    lo = __uint_as_float(a); hi = __uint_as_float(b);
}

// ---- cp.async helpers ------------------------------------------------------
__device__ __forceinline__ void cpa16(unsigned dst, const void* src) {
    asm volatile("cp.async.cg.shared.global [%0], [%1], 16;" :: "r"(dst), "l"(src));
}
#define CPA_COMMIT() asm volatile("cp.async.commit_group;")
#define CPA_WAIT2()  asm volatile("cp.async.wait_group 2;")

// ---------------------------------------------------------------------------
// GEMM v11: out[M,N] = X[M,K] @ W[K,N] (+bias)(+epilogue), 256 threads.
// TM=32, TN in {64,32}, TK=32. 4-stage cp.async pipeline (dynamic smem).
// Mainloop in packed f32x2: per k, b tile read as u64 pairs, a broadcast-
// duplicated (mov.b64 {r,r}); 4 FFMA2 replace 8 FFMA. A reads vectorized 4k.
// DUAL: blockIdx.z==1 computes X @ W2 -> out2 (no bias) in the same launch.
// EPI: 0=none, 1=relu, 2=leaky(0.01)
// ---------------------------------------------------------------------------
#define GAP 36                                   // A row pitch (floats)
#define GNS 4                                    // pipeline stages

template <int K, int N, int TN, int EPI, int DUAL>
__global__ __launch_bounds__(256) void sgemm11(
    const float* __restrict__ X, const float* __restrict__ W,
    const float* __restrict__ W2, const float* __restrict__ bias,
    float* __restrict__ out, float* __restrict__ out2) {

    constexpr int TK  = 32;
    constexpr int NIT = K / TK;                   // 4 or 8
    constexpr int NJ2 = TN / 32;                  // u64 cols per thread (2 or 1)
    constexpr int WCH = TN / 32;                  // B 16B chunks per thread

    extern __shared__ float sh[];
    float* Asm = sh;                              // GNS*32*GAP
    float* Bsm = sh + GNS * 32 * GAP;             // GNS*TK*TN

    const int t  = threadIdx.x;
    const int tx = t & 15;
    const int ty = t >> 4;
    const int m0 = blockIdx.y * 32;
    const int n0 = blockIdx.x * TN;

    const float* Wp = W;
    const float* bp = bias;
    float*       op = out;
    if (DUAL && blockIdx.z) { Wp = W2; bp = nullptr; op = out2; }

    const int am  = t >> 3;                       // 0..31
    const int akc = (t & 7) * 4;                  // k offset
    int br[WCH], bc[WCH];
#pragma unroll
    for (int p = 0; p < WCH; p++) {
        int q = (t + 256 * p);
        br[p] = q / (TN / 4);
        bc[p] = (q % (TN / 4)) * 4;
    }

    unsigned aSh = (unsigned)__cvta_generic_to_shared(Asm);
    unsigned bSh = (unsigned)__cvta_generic_to_shared(Bsm);

    auto issueTile = [&](int tile) {
        const int s  = tile & (GNS - 1);
        const int k0 = tile * TK;
        cpa16(aSh + (unsigned)(((s * 32 + am) * GAP + akc) * 4),
              &X[(m0 + am) * K + k0 + akc]);
#pragma unroll
        for (int p = 0; p < WCH; p++)
            cpa16(bSh + (unsigned)(((s * TK + br[p]) * TN + bc[p]) * 4),
                  &Wp[(k0 + br[p]) * N + n0 + bc[p]]);
    };

#pragma unroll
    for (int s = 0; s < GNS - 1; s++) { issueTile(s); CPA_COMMIT(); }

    u64 acc[2][NJ2];
#pragma unroll
    for (int i = 0; i < 2; i++)
#pragma unroll
        for (int j = 0; j < NJ2; j++) acc[i][j] = 0ull;

#pragma unroll 1
    for (int it = 0; it < NIT; it++) {
        const int s = it & (GNS - 1);
        CPA_WAIT2();
        __syncthreads();
        const float* Ar0 = &Asm[(s * 32 + ty * 2 + 0) * GAP];
        const float* Ar1 = &Asm[(s * 32 + ty * 2 + 1) * GAP];
        const float* Bk  = &Bsm[s * TK * TN];
#pragma unroll
        for (int k4 = 0; k4 < TK; k4 += 4) {
            float4 a0v = *(const float4*)&Ar0[k4];
            float4 a1v = *(const float4*)&Ar1[k4];
#pragma unroll
            for (int kk = 0; kk < 4; kk++) {
                float a0 = (&a0v.x)[kk];
                float a1 = (&a1v.x)[kk];
                u64 a0d = dup2(a0);
                u64 a1d = dup2(a1);
                if (NJ2 == 2) {
                    ulonglong2 b = *(const ulonglong2*)&Bk[(k4 + kk) * TN + tx * 4];
                    acc[0][0] = fma2(a0d, b.x, acc[0][0]);
                    acc[0][1] = fma2(a0d, b.y, acc[0][1]);
                    acc[1][0] = fma2(a1d, b.x, acc[1][0]);
                    acc[1][1] = fma2(a1d, b.y, acc[1][1]);
                } else {
                    u64 b = *(const u64*)&Bk[(k4 + kk) * TN + tx * 2];
                    acc[0][0] = fma2(a0d, b, acc[0][0]);
                    acc[1][0] = fma2(a1d, b, acc[1][0]);
                }
            }
        }
        if (it + GNS - 1 < NIT) issueTile(it + GNS - 1);
        CPA_COMMIT();
    }

    constexpr int CPT = NJ2 * 2;                 // scalar cols per thread
#pragma unroll
    for (int i = 0; i < 2; i++) {
        int m = m0 + ty * 2 + i;
#pragma unroll
        for (int j = 0; j < NJ2; j++) {
            float v0, v1;
            unpack2(acc[i][j], v0, v1);
            int n = n0 + tx * CPT + j * 2;
            float w0 = v0, w1 = v1;
            if (bp) { w0 += bp[n]; w1 += bp[n + 1]; }
            if (EPI == 1) { w0 = fmaxf(w0, 0.f); w1 = fmaxf(w1, 0.f); }
            if (EPI == 2) {
                w0 = (w0 >= 0.f) ? w0 : 0.01f * w0;
                w1 = (w1 >= 0.f) ? w1 : 0.01f * w1;
            }
            op[m * N + n]     = w0;
            op[m * N + n + 1] = w1;
        }
    }
}

#define GEMM_SMEM(TN) ((GNS * 32 * GAP + GNS * 32 * (TN)) * 4)

// ---------------------------------------------------------------------------
// Inclusive column prefix-sum over 1024 rows (256 cols), fused BN+relu:
//   h = (cumsum + bias) * (g * rsqrt(1+eps)) + bt ; relu
// ---------------------------------------------------------------------------
__global__ void cumsum_bn_relu_k(const float* __restrict__ in, float* __restrict__ out,
                                 const float* __restrict__ bias, const float* __restrict__ g,
                                 const float* __restrict__ bt) {
    const int C = HH;
    const int c = blockIdx.x;
    const int t = threadIdx.x;
    __shared__ float ssum[256];

    float v[4];
    float run = 0.f;
    const int base = t * 4;
#pragma unroll
    for (int r = 0; r < 4; r++) {
        v[r] = in[(base + r) * C + c];
        run += v[r];
        v[r] = run;
    }
    ssum[t] = run;
    __syncthreads();
    for (int off = 1; off < 256; off <<= 1) {
        float addv = 0.f;
        if (t >= off) addv = ssum[t - off];
        __syncthreads();
        if (t >= off) ssum[t] += addv;
        __syncthreads();
    }
    float excl = (t > 0) ? ssum[t - 1] : 0.f;
    float sc   = g[c] * rsqrtf(1.f + 1e-5f);
    float bb   = bias[c];
    float btc  = bt[c];
#pragma unroll
    for (int r = 0; r < 4; r++) {
        float h = (v[r] + excl + bb) * sc + btc;
        out[(base + r) * C + c] = fmaxf(h, 0.f);
    }
}

// ---------------------------------------------------------------------------
// Edge kernel v5: 64(i) x 32(j) pair tile, 256 threads, 4x2 micro, stride-16
// mapping, packed f32x2 + FMNMX relu. ~100KB smem -> ~2 CTAs/SM; 272 active
// blocks (tj >= 2*ti). Each i<j pair covered exactly once; writes both halves.
// ---------------------------------------------------------------------------
#define ESA 256
#define ESB 260
#define EDGE_SMEM ((64 * ESA + 32 * ESB + 256) * 4)

__global__ __launch_bounds__(256) void edge_k(
    const float* __restrict__ A, const float* __restrict__ Bm,
    const float* __restrict__ ew2, const float* __restrict__ eb2,
    float* __restrict__ out) {
    const int ti = blockIdx.y, tj = blockIdx.x;
    if (tj < 2 * ti) return;                 // tile entirely below diagonal

    extern __shared__ float sh[];
    float* As = sh;                          // 64 * 256
    float* Bs = sh + 64 * ESA;               // 32 * 260
    float* ws = sh + 64 * ESA + 32 * ESB;    // 256

    const int t = threadIdx.x;
    ws[t] = ew2[t];

    const int i0 = ti * 64, j0 = tj * 32;
#pragma unroll
    for (int p = 0; p < 16; p++) {
        int q = t + 256 * p;                 // A: 4096 float4 chunks
        int r = q >> 6;
        int c = (q & 63) << 2;
        *(float4*)&As[r * ESA + c] = *(const float4*)&A[(i0 + r) * HH + c];
    }
#pragma unroll
    for (int p = 0; p < 8; p++) {
        int q = t + 256 * p;                 // B: 2048 float4 chunks
        int r = q >> 6;
        int c = (q & 63) << 2;
        *(float4*)&Bs[r * ESB + c] = *(const float4*)&Bm[(j0 + r) * HH + c];
    }
    __syncthreads();

    const int tx = t & 15, ty = t >> 4;

    u64 acc[4][2];
#pragma unroll
    for (int di = 0; di < 4; di++)
#pragma unroll
        for (int dj = 0; dj < 2; dj++) acc[di][dj] = 0ull;

#pragma unroll 2
    for (int h = 0; h < HH; h += 4) {
        u64 w01 = *(const u64*)&ws[h];
        u64 w23 = *(const u64*)&ws[h + 2];
        u64 a01[4], a23[4], b01[2], b23[2];
#pragma unroll
        for (int d = 0; d < 4; d++) {
            ulonglong2 av = *(const ulonglong2*)&As[(ty + 16 * d) * ESA + h];
            a01[d] = av.x; a23[d] = av.y;
        }
#pragma unroll
        for (int d = 0; d < 2; d++) {
            ulonglong2 bv = *(const ulonglong2*)&Bs[(tx + 16 * d) * ESB + h];
            b01[d] = bv.x; b23[d] = bv.y;
        }
#pragma unroll
        for (int di = 0; di < 4; di++) {
#pragma unroll
            for (int dj = 0; dj < 2; dj++) {
                acc[di][dj] = fma2(relu2(add2(a01[di], b01[dj])), w01, acc[di][dj]);
                acc[di][dj] = fma2(relu2(add2(a23[di], b23[dj])), w23, acc[di][dj]);
            }
        }
    }

    const float e2 = eb2[0];
#pragma unroll
    for (int di = 0; di < 4; di++) {
#pragma unroll
        for (int dj = 0; dj < 2; dj++) {
            int gi = i0 + ty + 16 * di;
            int gj = j0 + tx + 16 * dj;
            float s = sum2(acc[di][dj]) + e2;
            if (gi < gj) {
                float pv = 1.f / (1.f + __expf(-s));
                out[gi * NN + gj] = pv;
                out[gj * NN + gi] = pv;
            } else if (gi == gj) {
                out[gi * NN + gi] = 0.f;
            }
        }
    }
}

// ---------------------------------------------------------------------------
extern "C" void kernel_launch(void* const* d_in, const int* in_sizes, int n_in,
                              void* d_out, int out_size) {
    (void)in_sizes; (void)n_in; (void)out_size;
    const float* x0  = (const float*)d_in[0];
    const float* w1a = (const float*)d_in[1];
    const float* b1a = (const float*)d_in[2];
    const float* g1  = (const float*)d_in[3];
    const float* bt1 = (const float*)d_in[4];
    const float* w1b = (const float*)d_in[5];
    const float* b1b = (const float*)d_in[6];
    const float* w2a = (const float*)d_in[7];
    const float* b2a = (const float*)d_in[8];
    const float* g2  = (const float*)d_in[9];
    const float* bt2 = (const float*)d_in[10];
    const float* w2b = (const float*)d_in[11];
    const float* b2b = (const float*)d_in[12];
    const float* lw1 = (const float*)d_in[13];
    const float* lb1 = (const float*)d_in[14];
    const float* lw2 = (const float*)d_in[15];
    const float* lb2 = (const float*)d_in[16];
    const float* ew1 = (const float*)d_in[17];
    const float* eb1 = (const float*)d_in[18];
    const float* ew2 = (const float*)d_in[19];
    const float* eb2 = (const float*)d_in[20];
    float* out = (float*)d_out;

    float *B1, *B2, *Ap, *Bp;
    cudaGetSymbolAddress((void**)&B1, g_buf1);
    cudaGetSymbolAddress((void**)&B2, g_buf2);
    cudaGetSymbolAddress((void**)&Ap, g_A);
    cudaGetSymbolAddress((void**)&Bp, g_B);

    const dim3 blk(256);
    const dim3 gA(4, 32);        // N=256, TN=64 -> 128 blocks
    const dim3 gB(4, 32);        // N=128, TN=32 -> 128 blocks
    const dim3 gD(4, 32, 2);     // dual edge GEMM -> 256 blocks
    const int s64 = GEMM_SMEM(64);
    const int s32 = GEMM_SMEM(32);

    (void)cudaFuncSetAttribute(sgemm11<128, 256, 64, 0, 0>, cudaFuncAttributeMaxDynamicSharedMemorySize, s64);
    (void)cudaFuncSetAttribute(sgemm11<256, 256, 64, 1, 0>, cudaFuncAttributeMaxDynamicSharedMemorySize, s64);
    (void)cudaFuncSetAttribute(sgemm11<256, 256, 64, 0, 0>, cudaFuncAttributeMaxDynamicSharedMemorySize, s64);
    (void)cudaFuncSetAttribute(sgemm11<256, 128, 32, 1, 0>, cudaFuncAttributeMaxDynamicSharedMemorySize, s32);
    (void)cudaFuncSetAttribute(sgemm11<128, 256, 64, 2, 0>, cudaFuncAttributeMaxDynamicSharedMemorySize, s64);
    (void)cudaFuncSetAttribute(sgemm11<256, 128, 32, 0, 0>, cudaFuncAttributeMaxDynamicSharedMemorySize, s32);
    (void)cudaFuncSetAttribute(sgemm11<128, 256, 64, 0, 1>, cudaFuncAttributeMaxDynamicSharedMemorySize, s64);
    (void)cudaFuncSetAttribute(edge_k, cudaFuncAttributeMaxDynamicSharedMemorySize, EDGE_SMEM);

    // GIN layer 1
    sgemm11<128, 256, 64, 0, 0><<<gA, blk, s64>>>(x0, w1a, nullptr, nullptr, B1, nullptr);
    cumsum_bn_relu_k<<<256, 256>>>(B1, B2, b1a, g1, bt1);
    sgemm11<256, 256, 64, 1, 0><<<gA, blk, s64>>>(B2, w1b, nullptr, b1b, B1, nullptr);

    // GIN layer 2
    sgemm11<256, 256, 64, 0, 0><<<gA, blk, s64>>>(B1, w2a, nullptr, nullptr, B2, nullptr);
    cumsum_bn_relu_k<<<256, 256>>>(B2, B1, b2a, g2, bt2);
    sgemm11<256, 128, 32, 1, 0><<<gB, blk, s32>>>(B1, w2b, nullptr, b2b, B2, nullptr);

    // Linear head
    sgemm11<128, 256, 64, 2, 0><<<gA, blk, s64>>>(B2, lw1, nullptr, lb1, B1, nullptr);
    sgemm11<256, 128, 32, 0, 0><<<gB, blk, s32>>>(B1, lw2, nullptr, lb2, B2, nullptr);

    // Edge halves in one launch: A = x@ew1[:128]+eb1 ; B = x@ew1[128:]
    sgemm11<128, 256, 64, 0, 1><<<gD, blk, s64>>>(B2, ew1, ew1 + 128 * HH, eb1, Ap, Bp);

    // Pairwise edge probabilities (64x32 tiles; blocks with tj>=2*ti active)
    edge_k<<<dim3(32, 16), dim3(256), EDGE_SMEM>>>(Ap, Bp, ew2, eb2, out);
}